// round 1
// baseline (speedup 1.0000x reference)
#include <cuda_runtime.h>
#include <cstdint>

#define B_    1024
#define CIN   672
#define COUT  128
#define HW    49
#define HWP   56    // padded spatial stride in Hs (conflict-free B frags)
#define KC    56    // K chunk size (672 = 12 * 56)
#define NKC   12
#define WS_LD 60    // padded W-tile stride (conflict-free A frags)

// smem (uint32 words): Hs [672][56] + Ws [128][60] + sc[672] + sh[672]
#define SMEM_WORDS (CIN*HWP + COUT*WS_LD + 2*CIN)
#define SMEM_BYTES (SMEM_WORDS * 4)   // 186624

__device__ __forceinline__ uint32_t f2tf32(float f) {
    uint32_t u;
    asm volatile("cvt.rna.tf32.f32 %0, %1;" : "=r"(u) : "f"(f));
    return u;
}

__device__ __forceinline__ void mma_tf32(float c[4],
    uint32_t a0, uint32_t a1, uint32_t a2, uint32_t a3,
    uint32_t b0, uint32_t b1)
{
    asm volatile(
        "mma.sync.aligned.m16n8k8.row.col.f32.tf32.tf32.f32 "
        "{%0,%1,%2,%3}, {%4,%5,%6,%7}, {%8,%9}, {%0,%1,%2,%3};"
        : "+f"(c[0]), "+f"(c[1]), "+f"(c[2]), "+f"(c[3])
        : "r"(a0), "r"(a1), "r"(a2), "r"(a3), "r"(b0), "r"(b1));
}

extern __shared__ uint32_t smem[];

__global__ void __launch_bounds__(256, 1)
bn_relu_conv1x1_kernel(const float* __restrict__ x,
                       const float* __restrict__ gamma,
                       const float* __restrict__ beta,
                       const float* __restrict__ rmean,
                       const float* __restrict__ rvar,
                       const float* __restrict__ W,
                       float* __restrict__ out)
{
    uint32_t* Hs = smem;                     // [672][56] tf32 (BN+ReLU'd x)
    uint32_t* Ws = Hs + CIN * HWP;           // [128][60] tf32 (W k-chunk)
    float*    sc = (float*)(Ws + COUT * WS_LD);
    float*    sh = sc + CIN;

    const int tid = threadIdx.x;
    const int b   = blockIdx.x;

    // ---- Phase 0: fold BN into per-channel scale/shift ----
    for (int c = tid; c < CIN; c += 256) {
        float inv = rsqrtf(rvar[c] + 1e-5f);
        float s   = gamma[c] * inv;
        sc[c] = s;
        sh[c] = beta[c] - rmean[c] * s;
    }
    __syncthreads();

    // ---- Phase 1: load x[b], apply BN+ReLU, convert tf32, store padded ----
    const float* xb = x + (size_t)b * (CIN * HW);
    for (int idx = tid; idx < CIN * HW; idx += 256) {
        int c = idx / HW;
        int s = idx - c * HW;
        float v = fmaf(xb[idx], sc[c], sh[c]);
        v = fmaxf(v, 0.0f);
        Hs[c * HWP + s] = f2tf32(v);
    }
    // zero padding columns 49..55 (keeps padded MMA outputs finite; unused)
    for (int i = tid; i < CIN * (HWP - HW); i += 256) {
        int c = i / (HWP - HW);
        int s = HW + (i - c * (HWP - HW));
        Hs[c * HWP + s] = 0u;
    }
    __syncthreads();

    const int warp = tid >> 5;
    const int lane = tid & 31;
    const int g = lane >> 2;      // groupID
    const int t = lane & 3;       // threadID_in_group
    const int m0 = warp * 16;     // each of 8 warps owns one 16-row M tile

    float acc[7][4];
    #pragma unroll
    for (int nt = 0; nt < 7; nt++) {
        #pragma unroll
        for (int i = 0; i < 4; i++) acc[nt][i] = 0.0f;
    }

    // ---- Phase 2: GEMM over 12 K-chunks ----
    for (int kc = 0; kc < NKC; kc++) {
        // stage W chunk [128][56] into Ws[128][60] (tf32)
        const float* Wc = W + kc * KC;
        for (int i = tid; i < COUT * KC; i += 256) {
            int o = i / KC;
            int k = i - o * KC;
            Ws[o * WS_LD + k] = f2tf32(Wc[o * CIN + k]);
        }
        __syncthreads();

        #pragma unroll
        for (int ks = 0; ks < KC / 8; ks++) {
            const int kk = ks * 8;
            // A fragments (m16n8k8 tf32): a0:(g,t) a1:(g+8,t) a2:(g,t+4) a3:(g+8,t+4)
            uint32_t a0 = Ws[(m0 + g)     * WS_LD + kk + t];
            uint32_t a1 = Ws[(m0 + g + 8) * WS_LD + kk + t];
            uint32_t a2 = Ws[(m0 + g)     * WS_LD + kk + t + 4];
            uint32_t a3 = Ws[(m0 + g + 8) * WS_LD + kk + t + 4];
            const int kg = kc * KC + kk;
            #pragma unroll
            for (int nt = 0; nt < 7; nt++) {
                // B fragments: b0:(k=t, n=g) b1:(k=t+4, n=g)
                uint32_t b0 = Hs[(kg + t)     * HWP + nt * 8 + g];
                uint32_t b1 = Hs[(kg + t + 4) * HWP + nt * 8 + g];
                mma_tf32(acc[nt], a0, a1, a2, a3, b0, b1);
            }
        }
        __syncthreads();   // protect Ws before next staging
    }

    // ---- Phase 3: store C fragments ----
    // c0:(g, 2t) c1:(g, 2t+1) c2:(g+8, 2t) c3:(g+8, 2t+1)
    float* ob = out + (size_t)b * (COUT * HW);
    const int r0 = m0 + g;
    #pragma unroll
    for (int nt = 0; nt < 7; nt++) {
        int col = nt * 8 + 2 * t;
        if (col < HW) {
            ob[r0 * HW + col]       = acc[nt][0];
            ob[(r0 + 8) * HW + col] = acc[nt][2];
        }
        if (col + 1 < HW) {
            ob[r0 * HW + col + 1]       = acc[nt][1];
            ob[(r0 + 8) * HW + col + 1] = acc[nt][3];
        }
    }
}

extern "C" void kernel_launch(void* const* d_in, const int* in_sizes, int n_in,
                              void* d_out, int out_size)
{
    const float* x     = (const float*)d_in[0];
    const float* gamma = (const float*)d_in[1];
    const float* beta  = (const float*)d_in[2];
    const float* rmean = (const float*)d_in[3];
    const float* rvar  = (const float*)d_in[4];
    const float* W     = (const float*)d_in[5];
    float* out = (float*)d_out;

    cudaFuncSetAttribute(bn_relu_conv1x1_kernel,
                         cudaFuncAttributeMaxDynamicSharedMemorySize, SMEM_BYTES);
    bn_relu_conv1x1_kernel<<<B_, 256, SMEM_BYTES>>>(x, gamma, beta, rmean, rvar, W, out);
}

// round 3
// speedup vs baseline: 3.3217x; 3.3217x over previous
#include <cuda_runtime.h>
#include <cstdint>

#define CIN   672
#define COUT  128
#define HW    49
#define NB    2
#define NREAL (NB*HW)        // 98
#define KC    32
#define NKC   21
#define GRID  (1024/NB)      // 512
#define BSTG  13             // ceil(32*98/256)

#define AS 36                // A tile row stride (words) -> banks 4g+t, conflict-free
#define BS 120               // B tile row stride (words) -> banks 24t+g, conflict-free
#define A_WORDS (COUT*AS)    // 4608
#define B_WORDS (KC*BS)      // 3840

#define OFF_SC 0
#define OFF_SH CIN
#define OFF_A0 (2*CIN)
#define OFF_A1 (OFF_A0 + A_WORDS)
#define OFF_B0 (OFF_A1 + A_WORDS)
#define OFF_B1 (OFF_B0 + B_WORDS)
#define SMEM_WORDS (OFF_B1 + B_WORDS)     // 18240 words
#define SMEM_BYTES (SMEM_WORDS*4)         // 72960 B -> 2 CTAs/SM
#define OFF_P OFF_A0                      // epilogue payload reuses A/B space
#define PS 113                            // payload row stride

__device__ __forceinline__ uint32_t f2tf32(float f) {
    uint32_t u;
    asm volatile("cvt.rna.tf32.f32 %0, %1;" : "=r"(u) : "f"(f));
    return u;
}
__device__ __forceinline__ uint32_t smem_u32(const void* p) {
    uint32_t a;
    asm("{ .reg .u64 t; cvta.to.shared.u64 t, %1; cvt.u32.u64 %0, t; }" : "=r"(a) : "l"(p));
    return a;
}
__device__ __forceinline__ void cp16(uint32_t dst, const void* src) {
    asm volatile("cp.async.cg.shared.global [%0], [%1], 16;" :: "r"(dst), "l"(src) : "memory");
}
__device__ __forceinline__ void mma_tf32(float c[4],
    uint32_t a0, uint32_t a1, uint32_t a2, uint32_t a3, uint32_t b0, uint32_t b1)
{
    asm volatile(
        "mma.sync.aligned.m16n8k8.row.col.f32.tf32.tf32.f32 "
        "{%0,%1,%2,%3}, {%4,%5,%6,%7}, {%8,%9}, {%0,%1,%2,%3};"
        : "+f"(c[0]), "+f"(c[1]), "+f"(c[2]), "+f"(c[3])
        : "r"(a0), "r"(a1), "r"(a2), "r"(a3), "r"(b0), "r"(b1));
}

extern __shared__ uint32_t sm[];

__global__ void __launch_bounds__(256, 2)
bn_conv_pipe(const float* __restrict__ x,
             const float* __restrict__ gamma,
             const float* __restrict__ beta,
             const float* __restrict__ rmean,
             const float* __restrict__ rvar,
             const float* __restrict__ W,
             float* __restrict__ out)
{
    const int tid  = threadIdx.x;
    const int wid  = tid >> 5;
    const int lane = tid & 31;
    const int g = lane >> 2, t = lane & 3;
    const int m0 = (wid & 3) * 32;        // 4 warps over M
    const int n0 = (wid >> 2) * 56;       // 2 warps over N
    const uint32_t sb = smem_u32(sm);

    float* scp = (float*)(sm + OFF_SC);
    float* shp = (float*)(sm + OFF_SH);

    // ---- prefetch A(0) = W[:, 0:32] via cp.async (raw fp32; HMMA truncates to tf32) ----
    #pragma unroll
    for (int it = 0; it < 4; it++) {
        int u = tid + it * 256;           // 1024 16B units: 128 rows x 8
        int o = u >> 3, j = u & 7;
        cp16(sb + (OFF_A0 + o * AS + j * 4) * 4, W + (size_t)o * CIN + j * 4);
    }
    asm volatile("cp.async.commit_group;" ::: "memory");

    // ---- BN fold (overlaps the cp.async) ----
    for (int c = tid; c < CIN; c += 256) {
        float inv = rsqrtf(rvar[c] + 1e-5f);
        float s = gamma[c] * inv;
        scp[c] = s;
        shp[c] = beta[c] - rmean[c] * s;
    }
    __syncthreads();

    const float* xb = x + (size_t)blockIdx.x * NB * CIN * HW;

    // ---- stage B(0): LDG -> BN+ReLU -> tf32 -> STS ----
    uint32_t breg[BSTG];
    #pragma unroll
    for (int j = 0; j < BSTG; j++) {
        int i = tid + j * 256;
        if (i < KC * NREAL) {
            int cl = i / NREAL, r = i - cl * NREAL;
            int b = r / HW, s = r - b * HW;
            float v = xb[(size_t)b * CIN * HW + (size_t)cl * HW + s];
            v = fmaxf(fmaf(v, scp[cl], shp[cl]), 0.0f);
            breg[j] = f2tf32(v);
        }
    }
    #pragma unroll
    for (int j = 0; j < BSTG; j++) {
        int i = tid + j * 256;
        if (i < KC * NREAL) {
            int cl = i / NREAL, r = i - cl * NREAL;
            sm[OFF_B0 + cl * BS + r] = breg[j];
        }
    }

    float acc[2][7][4];
    #pragma unroll
    for (int mt = 0; mt < 2; mt++)
        #pragma unroll
        for (int nt = 0; nt < 7; nt++)
            #pragma unroll
            for (int i = 0; i < 4; i++) acc[mt][nt][i] = 0.0f;

    // ---- main loop: double-buffered K chunks ----
    for (int kc = 0; kc < NKC; kc++) {
        const int buf = kc & 1;
        const uint32_t aoff   = buf ? OFF_A1 : OFF_A0;
        const uint32_t boff   = buf ? OFF_B1 : OFF_B0;
        const uint32_t aoff_n = buf ? OFF_A0 : OFF_A1;
        const uint32_t boff_n = buf ? OFF_B0 : OFF_B1;

        if (kc < NKC - 1) {
            // prefetch A(kc+1) into the buffer whose reads finished last iteration
            const float* Wc = W + (size_t)(kc + 1) * KC;
            #pragma unroll
            for (int it = 0; it < 4; it++) {
                int u = tid + it * 256;
                int o = u >> 3, j = u & 7;
                cp16(sb + (aoff_n + o * AS + j * 4) * 4, Wc + (size_t)o * CIN + j * 4);
            }
            asm volatile("cp.async.commit_group;" ::: "memory");
            asm volatile("cp.async.wait_group 1;" ::: "memory");  // A(kc) done
        } else {
            asm volatile("cp.async.wait_group 0;" ::: "memory");
        }
        __syncthreads();   // A(kc) + B(kc) visible to all warps

        // LDG B(kc+1) into registers (latency hidden under MMA below)
        if (kc < NKC - 1) {
            const int c0 = (kc + 1) * KC;
            #pragma unroll
            for (int j = 0; j < BSTG; j++) {
                int i = tid + j * 256;
                if (i < KC * NREAL) {
                    int cl = i / NREAL, r = i - cl * NREAL;
                    int b = r / HW, s = r - b * HW;
                    float v = xb[(size_t)b * CIN * HW + (size_t)(c0 + cl) * HW + s];
                    v = fmaxf(fmaf(v, scp[c0 + cl], shp[c0 + cl]), 0.0f);
                    breg[j] = f2tf32(v);
                }
            }
        }

        // ---- MMA over this chunk: 4 k8 steps ----
        const uint32_t* Ab = sm + aoff;
        const uint32_t* Bb = sm + boff;
        #pragma unroll
        for (int ks = 0; ks < 4; ks++) {
            const int kk = ks * 8;
            uint32_t a[2][4];
            #pragma unroll
            for (int mt = 0; mt < 2; mt++) {
                const int r0 = m0 + mt * 16 + g;
                a[mt][0] = Ab[r0 * AS + kk + t];
                a[mt][1] = Ab[(r0 + 8) * AS + kk + t];
                a[mt][2] = Ab[r0 * AS + kk + t + 4];
                a[mt][3] = Ab[(r0 + 8) * AS + kk + t + 4];
            }
            #pragma unroll
            for (int nt = 0; nt < 7; nt++) {
                uint32_t b0 = Bb[(kk + t) * BS + n0 + nt * 8 + g];
                uint32_t b1 = Bb[(kk + t + 4) * BS + n0 + nt * 8 + g];
                mma_tf32(acc[0][nt], a[0][0], a[0][1], a[0][2], a[0][3], b0, b1);
                mma_tf32(acc[1][nt], a[1][0], a[1][1], a[1][2], a[1][3], b0, b1);
            }
        }

        // STS B(kc+1) into the next buffer
        if (kc < NKC - 1) {
            #pragma unroll
            for (int j = 0; j < BSTG; j++) {
                int i = tid + j * 256;
                if (i < KC * NREAL) {
                    int cl = i / NREAL, r = i - cl * NREAL;
                    sm[boff_n + cl * BS + r] = breg[j];
                }
            }
        }
        __syncthreads();   // gate buffer reuse for next iteration
    }

    // ---- epilogue: acc -> SMEM payload -> coalesced STG ----
    float* P = (float*)(sm + OFF_P);
    #pragma unroll
    for (int mt = 0; mt < 2; mt++) {
        const int rb = m0 + mt * 16 + g;
        #pragma unroll
        for (int nt = 0; nt < 7; nt++) {
            const int cb = n0 + nt * 8 + 2 * t;
            P[rb * PS + cb]           = acc[mt][nt][0];
            P[rb * PS + cb + 1]       = acc[mt][nt][1];
            P[(rb + 8) * PS + cb]     = acc[mt][nt][2];
            P[(rb + 8) * PS + cb + 1] = acc[mt][nt][3];
        }
    }
    __syncthreads();

    float* ob = out + (size_t)blockIdx.x * NB * COUT * HW;
    #pragma unroll 4
    for (int idx = tid; idx < NB * COUT * HW; idx += 256) {
        int b = idx / (COUT * HW);
        int rem = idx - b * (COUT * HW);
        int o = rem / HW, s = rem - o * HW;
        ob[idx] = P[o * PS + b * HW + s];
    }
}

extern "C" void kernel_launch(void* const* d_in, const int* in_sizes, int n_in,
                              void* d_out, int out_size)
{
    const float* x     = (const float*)d_in[0];
    const float* gamma = (const float*)d_in[1];
    const float* beta  = (const float*)d_in[2];
    const float* rmean = (const float*)d_in[3];
    const float* rvar  = (const float*)d_in[4];
    const float* W     = (const float*)d_in[5];
    float* out = (float*)d_out;

    cudaFuncSetAttribute(bn_conv_pipe,
                         cudaFuncAttributeMaxDynamicSharedMemorySize, SMEM_BYTES);
    bn_conv_pipe<<<GRID, 256, SMEM_BYTES>>>(x, gamma, beta, rmean, rvar, W, out);
}

// round 4
// speedup vs baseline: 5.5422x; 1.6685x over previous
#include <cuda_runtime.h>
#include <cuda_fp16.h>
#include <cstdint>

#define CIN   672
#define COUT  128
#define HW    49
#define NB    2
#define NREAL 98          // NB*HW
#define NPAD  112
#define KC    32
#define NKC   21
#define GRID  512

#define LDA 20            // A row stride (half2 words): conflict-free frag reads
#define LDB 24            // B row stride (half2 words): conflict-free frag reads
#define A_WORDS (COUT*LDA)   // 2560
#define B_WORDS (NPAD*LDB)   // 2688

// word offsets in dynamic smem
#define OFF_SS 0                         // float2[672] (scale, shift) = 1344 words
#define OFF_A0 1344
#define OFF_A1 (OFF_A0 + A_WORDS)
#define OFF_B0 (OFF_A1 + A_WORDS)
#define OFF_B1 (OFF_B0 + B_WORDS)
#define PIPE_WORDS (OFF_B1 + B_WORDS)    // 11840 words
#define PS 113
#define P_WORDS (COUT*PS)                // 14464 words
#define SMEM_WORDS (P_WORDS > PIPE_WORDS ? P_WORDS : PIPE_WORDS)
#define SMEM_BYTES (SMEM_WORDS*4)        // 57856 -> 2 CTAs/SM

__device__ __forceinline__ void hmma16816(float c[4],
    uint32_t a0, uint32_t a1, uint32_t a2, uint32_t a3, uint32_t b0, uint32_t b1)
{
    asm volatile(
        "mma.sync.aligned.m16n8k16.row.col.f32.f16.f16.f32 "
        "{%0,%1,%2,%3}, {%4,%5,%6,%7}, {%8,%9}, {%0,%1,%2,%3};"
        : "+f"(c[0]), "+f"(c[1]), "+f"(c[2]), "+f"(c[3])
        : "r"(a0), "r"(a1), "r"(a2), "r"(a3), "r"(b0), "r"(b1));
}
__device__ __forceinline__ uint32_t pack_h2(float lo, float hi) {
    __half2 h = __floats2half2_rn(lo, hi);
    return *reinterpret_cast<uint32_t*>(&h);
}

extern __shared__ uint32_t sm[];

__global__ void __launch_bounds__(256, 2)
bn_conv_f16(const float* __restrict__ x,
            const float* __restrict__ gamma,
            const float* __restrict__ beta,
            const float* __restrict__ rmean,
            const float* __restrict__ rvar,
            const float* __restrict__ W,
            float* __restrict__ out)
{
    const int tid  = threadIdx.x;
    const int wid  = tid >> 5;
    const int lane = tid & 31;
    const int g = lane >> 2, t = lane & 3;
    const int m0 = (wid & 3) * 32;        // 4 warps over M=128
    const int n0 = (wid >> 2) * 56;       // 2 warps over N=112

    float2* ssc = (float2*)(sm + OFF_SS);
    const float* sscf = (const float*)ssc;

    // ---- prologue: BN fold + zero B buffers ----
    for (int c = tid; c < CIN; c += 256) {
        float inv = rsqrtf(rvar[c] + 1e-5f);
        float s = gamma[c] * inv;
        ssc[c] = make_float2(s, beta[c] - rmean[c] * s);
    }
    for (int i = tid; i < 2 * B_WORDS; i += 256) sm[OFF_B0 + i] = 0u;

    // ---- per-thread staging constants ----
    // B: 784 pair-elems = 98 n x 8 pairs; lane-consecutive n (coalesced LDG)
    int xoff[4], bsts[4], klr[4];
    #pragma unroll
    for (int j = 0; j < 4; j++) {
        int i = tid + j * 256;
        if (i > 783) i = 783;             // clamp (j=3 guarded at use)
        int p = i / 98;
        int n = i - 98 * p;
        int tp = p & 3, ks = p >> 2;
        int kl = ks * 16 + tp * 2;
        int b = (n >= HW) ? 1 : 0;
        int s = n - HW * b;
        xoff[j] = (b * CIN + kl) * HW + s;
        bsts[j] = n * LDB + 2 * (p ^ (n & 7));
        klr[j]  = kl;
    }
    const bool v3 = (tid < 16);           // j=3 valid only for i<784

    // A: 1024 float4 per chunk = 128 rows x 8 quads
    int woff[4], asts[4];
    #pragma unroll
    for (int it = 0; it < 4; it++) {
        int idx = tid + it * 256;
        int m = idx >> 3, q = idx & 7;
        woff[it] = m * CIN + 4 * q;
        asts[it] = m * LDA + 2 * q;
    }

    const float* xb = x + (size_t)blockIdx.x * NB * CIN * HW;
    __syncthreads();

    float acc[2][7][4];
    #pragma unroll
    for (int mt = 0; mt < 2; mt++)
        #pragma unroll
        for (int nt = 0; nt < 7; nt++)
            #pragma unroll
            for (int i = 0; i < 4; i++) acc[mt][nt][i] = 0.0f;

    // frag address bases (constant across chunks)
    const int ar00 = (m0 + g) * LDA;          // mt=0 rows g / g+8
    const int ar01 = (m0 + g + 8) * LDA;
    const int ar10 = (m0 + 16 + g) * LDA;     // mt=1
    const int ar11 = (m0 + 24 + g) * LDA;
    const int bnb  = (n0 + g) * LDB;          // n&7 == g for all nt

    float xv[4][4];

    #pragma unroll 1
    for (int kc = -1; kc < NKC; kc++) {
        const int kcn = kc + 1;

        // ---- issue x LDGs for chunk kcn (hidden under the MMA below) ----
        if (kcn < NKC) {
            const int xadd = kcn * (KC * HW);
            #pragma unroll
            for (int j = 0; j < 4; j++) {
                if (j < 3 || v3) {
                    const float* px = xb + xoff[j] + xadd;
                    xv[j][0] = px[0];
                    xv[j][1] = px[HW];
                    xv[j][2] = px[8 * HW];
                    xv[j][3] = px[9 * HW];
                }
            }
        }

        // ---- MMA on chunk kc ----
        if (kc >= 0) {
            const uint32_t* As = sm + ((kc & 1) ? OFF_A1 : OFF_A0);
            const uint32_t* Bs = sm + ((kc & 1) ? OFF_B1 : OFF_B0);
            #pragma unroll
            for (int ks = 0; ks < 2; ks++) {
                const int ka = ks * 8 + t;
                uint32_t a0[4], a1[4];
                a0[0] = As[ar00 + ka];     a0[1] = As[ar01 + ka];
                a0[2] = As[ar00 + ka + 4]; a0[3] = As[ar01 + ka + 4];
                a1[0] = As[ar10 + ka];     a1[1] = As[ar11 + ka];
                a1[2] = As[ar10 + ka + 4]; a1[3] = As[ar11 + ka + 4];
                const int bsw = bnb + 2 * ((ks * 4 + t) ^ g);
                #pragma unroll
                for (int nt = 0; nt < 7; nt++) {
                    uint2 b = *(const uint2*)&Bs[bsw + nt * 8 * LDB];
                    hmma16816(acc[0][nt], a0[0], a0[1], a0[2], a0[3], b.x, b.y);
                    hmma16816(acc[1][nt], a1[0], a1[1], a1[2], a1[3], b.x, b.y);
                }
            }
        }

        // ---- stage chunk kcn into the other buffer ----
        if (kcn < NKC) {
            uint32_t* An = sm + ((kcn & 1) ? OFF_A1 : OFF_A0);
            uint32_t* Bn = sm + ((kcn & 1) ? OFF_B1 : OFF_B0);

            // A = W chunk (L2-resident): LDG.128 -> cvt -> STS.64
            const float* Wc = W + kcn * KC;
            #pragma unroll
            for (int it = 0; it < 4; it++) {
                float4 w = *(const float4*)(Wc + woff[it]);
                uint2 hw;
                hw.x = pack_h2(w.x, w.y);
                hw.y = pack_h2(w.z, w.w);
                *(uint2*)(An + asts[it]) = hw;
            }

            // B: BN + ReLU + cvt on the preloaded x
            #pragma unroll
            for (int j = 0; j < 4; j++) {
                if (j < 3 || v3) {
                    const int c = kcn * KC + klr[j];
                    float4 s0 = *(const float4*)(sscf + 2 * c);
                    float4 s1 = *(const float4*)(sscf + 2 * (c + 8));
                    float h0 = fmaxf(fmaf(xv[j][0], s0.x, s0.y), 0.0f);
                    float h1 = fmaxf(fmaf(xv[j][1], s0.z, s0.w), 0.0f);
                    float h2 = fmaxf(fmaf(xv[j][2], s1.x, s1.y), 0.0f);
                    float h3 = fmaxf(fmaf(xv[j][3], s1.z, s1.w), 0.0f);
                    uint2 hb;
                    hb.x = pack_h2(h0, h1);
                    hb.y = pack_h2(h2, h3);
                    *(uint2*)(Bn + bsts[j]) = hb;
                }
            }
        }
        __syncthreads();
    }

    // ---- epilogue: acc -> SMEM payload P[o][n] -> coalesced vector STG ----
    float* P = (float*)sm;
    #pragma unroll
    for (int mt = 0; mt < 2; mt++) {
        const int rb = m0 + mt * 16 + g;
        #pragma unroll
        for (int nt = 0; nt < 7; nt++) {
            const int cb = n0 + nt * 8 + 2 * t;
            P[rb * PS + cb]           = acc[mt][nt][0];
            P[rb * PS + cb + 1]       = acc[mt][nt][1];
            P[(rb + 8) * PS + cb]     = acc[mt][nt][2];
            P[(rb + 8) * PS + cb + 1] = acc[mt][nt][3];
        }
    }
    __syncthreads();

    float* ob = out + (size_t)blockIdx.x * NB * COUT * HW;
    #pragma unroll
    for (int it = 0; it < 13; it++) {
        int f0 = (tid + it * 256) * 4;
        if (f0 < NB * COUT * HW) {
            float4 v;
            #pragma unroll
            for (int e = 0; e < 4; e++) {
                int f = f0 + e;
                int b = (f >= COUT * HW) ? 1 : 0;
                int r = f - b * (COUT * HW);
                int o = r / HW;
                int s = r - o * HW;
                ((float*)&v)[e] = P[o * PS + b * HW + s];
            }
            *(float4*)(ob + f0) = v;
        }
    }
}

extern "C" void kernel_launch(void* const* d_in, const int* in_sizes, int n_in,
                              void* d_out, int out_size)
{
    const float* x     = (const float*)d_in[0];
    const float* gamma = (const float*)d_in[1];
    const float* beta  = (const float*)d_in[2];
    const float* rmean = (const float*)d_in[3];
    const float* rvar  = (const float*)d_in[4];
    const float* W     = (const float*)d_in[5];
    float* out = (float*)d_out;

    cudaFuncSetAttribute(bn_conv_f16,
                         cudaFuncAttributeMaxDynamicSharedMemorySize, SMEM_BYTES);
    bn_conv_f16<<<GRID, 256, SMEM_BYTES>>>(x, gamma, beta, rmean, rvar, W, out);
}